// round 14
// baseline (speedup 1.0000x reference)
#include <cuda_runtime.h>

// QualityAwarePatchAugment — GB300 sm_103a — R10: warp-autonomous.
// One WARP owns one patch (4096 warps = 1024 blocks x 4 warps). Per warp:
// loop 8 groups of 4 batches (lane: b4=lane>>3, l8=lane&7); per group load
// 8 float4/lane (same 8x64B coalescing + MLP-8 as R8's best load phase),
// width-8 shuffle reduce, l8==0 lanes fold that batch's quality/sum into
// scalar accumulators. NO __syncthreads, NO smem anywhere: warps free-run so
// DRAM loads/stores from ~28 independent warps/SM mix at the finest grain
// (the block-phase seams that pinned R3/R5/R8 at ~4.3 TB/s are gone).
// Apply re-reads the patch from L2 (within-warp reuse distance ~32 KB —
// the mechanism R7 proved works).

__device__ __forceinline__ float clipf(float v) {
    return fminf(fmaxf(v, 0.0f), 1.0f);
}

__global__ void __launch_bounds__(128) fused_kernel(
    const float4* __restrict__ img,
    const float4* __restrict__ noise,
    float4*       __restrict__ out,
    const float*  __restrict__ r_strong,
    const float*  __restrict__ r_drop,
    const float*  __restrict__ r_else,
    const float*  __restrict__ bright_f,
    const float*  __restrict__ contrast_f,
    const float*  __restrict__ slight_f,
    const int*    __restrict__ aug_choice,
    const int*    __restrict__ slight_choice)
{
    const int p    = (blockIdx.x << 2) + (threadIdx.x >> 5);  // patch 0..4095
    const int lane = threadIdx.x & 31;
    const int b4   = lane >> 3;             // batch sub-index 0..3
    const int l8   = lane & 7;              // 8 lanes per batch
    const int ph   = p >> 6;
    const int pw   = p & 63;

    // Per-warp scalar prefetch (lanes 0..7), distributed later by shuffle.
    float scal = 0.0f;
    if (lane < 8) {
        switch (lane) {
            case 0: scal = r_strong[p];                       break;
            case 1: scal = r_drop[p];                         break;
            case 2: scal = r_else[p];                         break;
            case 3: scal = bright_f[p];                       break;
            case 4: scal = contrast_f[p];                     break;
            case 5: scal = slight_f[p];                       break;
            case 6: scal = __int_as_float(aug_choice[p]);     break;
            default: scal = __int_as_float(slight_choice[p]); break;
        }
    }

    const int pbase = (ph << 12) + (pw << 2);   // float4 idx of (b=0,row0)

    // ---- Stats: 8 groups x 4 batches; immediate per-batch quality fold ----
    float qs = 0.0f, tot = 0.0f;        // valid on l8==0 lanes
    #pragma unroll
    for (int g = 0; g < 8; g++) {
        const int b    = (g << 2) + b4;           // batch 0..31
        const int base = (b << 18) + pbase;       // img row stride = 256 f4
        float s = 0.0f, s2 = 0.0f;
        #pragma unroll
        for (int k = 0; k < 8; k++) {             // MLP-8 chunk
            const int fi = l8 + (k << 3);         // slot 0..63
            const float4 v = img[base + ((fi >> 2) << 8) + (fi & 3)];
            s  += v.x + v.y + v.z + v.w;
            s2 += v.x * v.x + v.y * v.y + v.z * v.z + v.w * v.w;
        }
        #pragma unroll
        for (int off = 4; off; off >>= 1) {       // width-8 reduce
            s  += __shfl_down_sync(0xffffffffu, s,  off, 8);
            s2 += __shfl_down_sync(0xffffffffu, s2, off, 8);
        }
        if (l8 == 0) {                            // fold batch quality now
            const float mean = s * (1.0f / 256.0f);
            float var = (s2 - s * s * (1.0f / 256.0f)) * (1.0f / 255.0f);
            var = fmaxf(var, 0.0f);               // ddof=1
            const float iq = 1.0f - 2.0f * fabsf(mean - 0.5f);
            qs  += (sqrtf(var) + iq + var) * (1.0f / 3.0f);
            tot += s;
        }
    }
    // Combine the 4 accumulator lanes (0,8,16,24) -> all lanes.
    float q = 0.0f, mp = 0.0f;
    #pragma unroll
    for (int src = 0; src < 32; src += 8) {
        q  += __shfl_sync(0xffffffffu, qs,  src);
        mp += __shfl_sync(0xffffffffu, tot, src);
    }
    q *= (1.0f / 32.0f);
    const float mpp = mp * (1.0f / 8192.0f);      // 32 batches * 256 px

    // ---- Decide (all lanes redundantly) -----------------------------------
    const float sc0 = __shfl_sync(0xffffffffu, scal, 0);
    const float sc1 = __shfl_sync(0xffffffffu, scal, 1);
    const float sc2 = __shfl_sync(0xffffffffu, scal, 2);
    const float sc3 = __shfl_sync(0xffffffffu, scal, 3);
    const float sc4 = __shfl_sync(0xffffffffu, scal, 4);
    const float sc5 = __shfl_sync(0xffffffffu, scal, 5);
    const float sc6 = __shfl_sync(0xffffffffu, scal, 6);
    const float sc7 = __shfl_sync(0xffffffffu, scal, 7);

    const bool low    = q < 0.7f;
    const bool strong = low && (sc0 < 0.8f);
    const bool drop   = low && (q < 0.3f) && (sc1 < 0.1f);
    const bool els    = (!low) && (sc2 < 0.3f);

    int code = 0;
    if (strong) code = __float_as_int(sc6) + 1;   // aug_choice + 1
    if (els)    code = __float_as_int(sc7) + 5;   // slight_choice + 5
    if (drop)   code = 7;

    float param = 0.0f;
    switch (code) {
        case 1: param = 0.1f;  break;
        case 3: param = sc3;   break;   // bright_f
        case 4: param = sc4;   break;   // contrast_f
        case 5: param = 0.05f; break;
        case 6: param = sc5;   break;   // slight_f
        default: break;
    }

    // ---- Apply: re-read patch (L2 hits), transform, store ------------------
    if (code == 0) {                              // identity (~20%)
        #pragma unroll
        for (int g = 0; g < 8; g++) {
            const int base = (((g << 2) + b4) << 18) + pbase;
            #pragma unroll
            for (int k = 0; k < 8; k++) {
                const int fi = l8 + (k << 3);
                const int gi = base + ((fi >> 2) << 8) + (fi & 3);
                out[gi] = img[gi];
            }
        }
    } else if (code == 1 || code == 5) {          // noise / slight noise
        #pragma unroll
        for (int g = 0; g < 8; g++) {
            const int base = (((g << 2) + b4) << 18) + pbase;
            #pragma unroll
            for (int k = 0; k < 8; k++) {
                const int fi = l8 + (k << 3);
                const int gi = base + ((fi >> 2) << 8) + (fi & 3);
                const float4 v = img[gi];             // L2 hit
                const float4 n = __ldcs(&noise[gi]);  // DRAM, single-use
                float4 o;
                o.x = clipf(fmaf(param, n.x, v.x));
                o.y = clipf(fmaf(param, n.y, v.y));
                o.z = clipf(fmaf(param, n.z, v.z));
                o.w = clipf(fmaf(param, n.w, v.w));
                out[gi] = o;
            }
        }
    } else if (code == 2) {                       // 3x3 blur, zero-pad in patch
        const float inv9 = 1.0f / 9.0f;
        const float* imgf = (const float*)img;
        #pragma unroll
        for (int g = 0; g < 8; g++) {
            const int base = (((g << 2) + b4) << 18) + pbase;
            #pragma unroll
            for (int k = 0; k < 8; k++) {
                const int fi  = l8 + (k << 3);
                const int row = fi >> 2;
                const int c4  = fi & 3;
                float a0 = 0.f, a1 = 0.f, a2 = 0.f, a3 = 0.f;
                #pragma unroll
                for (int dr = -1; dr <= 1; dr++) {
                    const int r = row + dr;
                    if (r < 0 || r > 15) continue;        // zero padding
                    const int bf4 = base + (r << 8) + c4;
                    const int bpx = bf4 << 2;
                    const float4 vv = img[bf4];           // L1/L2 hit
                    const float lft = (c4 > 0) ? __ldg(imgf + bpx - 1) : 0.0f;
                    const float rgt = (c4 < 3) ? __ldg(imgf + bpx + 4) : 0.0f;
                    a0 += lft  + vv.x + vv.y;
                    a1 += vv.x + vv.y + vv.z;
                    a2 += vv.y + vv.z + vv.w;
                    a3 += vv.z + vv.w + rgt;
                }
                out[base + (row << 8) + c4] =
                    make_float4(a0 * inv9, a1 * inv9, a2 * inv9, a3 * inv9);
            }
        }
    } else if (code == 3 || code == 6) {          // brightness variants
        #pragma unroll
        for (int g = 0; g < 8; g++) {
            const int base = (((g << 2) + b4) << 18) + pbase;
            #pragma unroll
            for (int k = 0; k < 8; k++) {
                const int fi = l8 + (k << 3);
                const int gi = base + ((fi >> 2) << 8) + (fi & 3);
                const float4 v = img[gi];
                float4 o;
                o.x = clipf(v.x * param);
                o.y = clipf(v.y * param);
                o.z = clipf(v.z * param);
                o.w = clipf(v.w * param);
                out[gi] = o;
            }
        }
    } else if (code == 4) {                       // contrast about m_pp
        #pragma unroll
        for (int g = 0; g < 8; g++) {
            const int base = (((g << 2) + b4) << 18) + pbase;
            #pragma unroll
            for (int k = 0; k < 8; k++) {
                const int fi = l8 + (k << 3);
                const int gi = base + ((fi >> 2) << 8) + (fi & 3);
                const float4 v = img[gi];
                float4 o;
                o.x = clipf(fmaf(v.x - mpp, param, mpp));
                o.y = clipf(fmaf(v.y - mpp, param, mpp));
                o.z = clipf(fmaf(v.z - mpp, param, mpp));
                o.w = clipf(fmaf(v.w - mpp, param, mpp));
                out[gi] = o;
            }
        }
    } else {                                      // 7: drop -> zeros, no re-read
        const float4 z = make_float4(0.f, 0.f, 0.f, 0.f);
        #pragma unroll
        for (int g = 0; g < 8; g++) {
            const int base = (((g << 2) + b4) << 18) + pbase;
            #pragma unroll
            for (int k = 0; k < 8; k++) {
                const int fi = l8 + (k << 3);
                out[base + ((fi >> 2) << 8) + (fi & 3)] = z;
            }
        }
    }
}

extern "C" void kernel_launch(void* const* d_in, const int* in_sizes, int n_in,
                              void* d_out, int out_size)
{
    // 4096 patches, 4 warps per 128-thread block -> 1024 blocks.
    fused_kernel<<<1024, 128>>>(
        (const float4*)d_in[0],   // img
        (const float4*)d_in[1],   // noise
        (float4*)d_out,
        (const float*)d_in[2],    // r_strong
        (const float*)d_in[3],    // r_drop
        (const float*)d_in[4],    // r_else
        (const float*)d_in[5],    // bright_f
        (const float*)d_in[6],    // contrast_f
        (const float*)d_in[7],    // slight_f
        (const int*)d_in[8],      // aug_choice
        (const int*)d_in[9]);     // slight_choice
}

// round 15
// speedup vs baseline: 3.4515x; 3.4515x over previous
#include <cuda_runtime.h>

// QualityAwarePatchAugment — GB300 sm_103a — R11.
// R8's proven structure (fused, ONE barrier, register patch cache, redundant
// per-warp fold, smem only for blur) at finer thread granularity:
//   512 threads per patch, 4 float4 per thread (16 landing regs vs 32).
// Rationale: R8 was register-limited to 4 blocks/SM (occ 46%) by its 8-f4
// cache; R1's apply kernel proved this access pattern runs at 5.08 TB/s when
// occupancy is ~77%. Halving per-thread MLP while adding 50% more resident
// threads raises aggregate in-flight loads. launch_bounds(512,3) caps regs
// at 42 — enough for a 4-deep load chain (R4's kill was 8-deep into 40).

__device__ __forceinline__ float clipf(float v) {
    return fminf(fmaxf(v, 0.0f), 1.0f);
}

__global__ void __launch_bounds__(512, 3) fused_kernel(
    const float4* __restrict__ img,
    const float4* __restrict__ noise,
    float4*       __restrict__ out,
    const float*  __restrict__ r_strong,
    const float*  __restrict__ r_drop,
    const float*  __restrict__ r_else,
    const float*  __restrict__ bright_f,
    const float*  __restrict__ contrast_f,
    const float*  __restrict__ slight_f,
    const int*    __restrict__ aug_choice,
    const int*    __restrict__ slight_choice)
{
    __shared__ float sm[32 * 256];          // patch tile; used ONLY for blur
    __shared__ float sh_s[32], sh_s2[32];
    __shared__ float s_scal[8];

    const int p    = blockIdx.x;            // patch index = ph*64 + pw
    const int ph   = p >> 6;
    const int pw   = p & 63;
    const int t    = threadIdx.x;            // 0..511
    const int b    = t >> 4;                 // batch 0..31 (16 thr/batch)
    const int l16  = t & 15;                 // 16 threads per batch
    const int lane = t & 31;

    // Prefetch decision scalars (before the barrier).
    if (t < 8) {
        float v;
        switch (t) {
            case 0: v = r_strong[p];                       break;
            case 1: v = r_drop[p];                         break;
            case 2: v = r_else[p];                         break;
            case 3: v = bright_f[p];                       break;
            case 4: v = contrast_f[p];                     break;
            case 5: v = slight_f[p];                       break;
            case 6: v = __int_as_float(aug_choice[p]);     break;
            default: v = __int_as_float(slight_choice[p]); break;
        }
        s_scal[t] = v;
    }

    // float4 base of (batch b, patch row 0); img row stride = 256 float4.
    const int f4base = (b << 18) + (ph << 12) + (pw << 2);

    // ---- Phase 1: load 4 float4s into registers (cache == landing regs) ---
    float4 v[4];
    float s = 0.0f, s2 = 0.0f;
    #pragma unroll
    for (int k = 0; k < 4; k++) {
        const int fi = l16 + (k << 4);      // slot 0..63; row=fi>>2, c4=fi&3
        v[k] = img[f4base + ((fi >> 2) << 8) + (fi & 3)];
        s  += v[k].x + v[k].y + v[k].z + v[k].w;
        s2 += v[k].x * v[k].x + v[k].y * v[k].y
            + v[k].z * v[k].z + v[k].w * v[k].w;
    }
    #pragma unroll
    for (int off = 8; off; off >>= 1) {     // width-16 reduce within batch
        s  += __shfl_down_sync(0xffffffffu, s,  off, 16);
        s2 += __shfl_down_sync(0xffffffffu, s2, off, 16);
    }
    if (l16 == 0) { sh_s[b] = s; sh_s2[b] = s2; }
    __syncthreads();                        // the only unconditional barrier

    // ---- Phase 2: redundant per-warp butterfly fold (all lanes get q,mpp) -
    float q, mpp;
    {
        const float bs  = sh_s[lane];
        const float bs2 = sh_s2[lane];
        const float mean = bs * (1.0f / 256.0f);
        float var = (bs2 - bs * bs * (1.0f / 256.0f)) * (1.0f / 255.0f); // ddof=1
        var = fmaxf(var, 0.0f);
        const float sd = sqrtf(var);
        const float iq = 1.0f - 2.0f * fabsf(mean - 0.5f);
        float qs  = (sd + iq + var) * (1.0f / 3.0f);
        float tot = bs;
        #pragma unroll
        for (int off = 16; off; off >>= 1) {
            qs  += __shfl_xor_sync(0xffffffffu, qs,  off);
            tot += __shfl_xor_sync(0xffffffffu, tot, off);
        }
        q   = qs  * (1.0f / 32.0f);
        mpp = tot * (1.0f / 8192.0f);       // 32 batches * 256 px
    }

    const bool low    = q < 0.7f;
    const bool strong = low && (s_scal[0] < 0.8f);
    const bool drop   = low && (q < 0.3f) && (s_scal[1] < 0.1f);
    const bool els    = (!low) && (s_scal[2] < 0.3f);

    int code = 0;
    if (strong) code = __float_as_int(s_scal[6]) + 1;   // aug_choice + 1
    if (els)    code = __float_as_int(s_scal[7]) + 5;   // slight_choice + 5
    if (drop)   code = 7;

    float param = 0.0f;
    switch (code) {
        case 1: param = 0.1f;       break;
        case 3: param = s_scal[3];  break;   // bright_f
        case 4: param = s_scal[4];  break;   // contrast_f
        case 5: param = 0.05f;      break;
        case 6: param = s_scal[5];  break;   // slight_f
        default: break;
    }

    // ---- Phase 3: apply (block-uniform branch; data lives in registers) ---
    if (code == 0) {                              // identity (~20%)
        #pragma unroll
        for (int k = 0; k < 4; k++) {
            const int fi = l16 + (k << 4);
            out[f4base + ((fi >> 2) << 8) + (fi & 3)] = v[k];
        }
    } else if (code == 1 || code == 5) {          // noise / slight noise
        #pragma unroll
        for (int k = 0; k < 4; k++) {
            const int fi = l16 + (k << 4);
            const int gi = f4base + ((fi >> 2) << 8) + (fi & 3);
            const float4 n = __ldcs(&noise[gi]);
            float4 o;
            o.x = clipf(fmaf(param, n.x, v[k].x));
            o.y = clipf(fmaf(param, n.y, v[k].y));
            o.z = clipf(fmaf(param, n.z, v[k].z));
            o.w = clipf(fmaf(param, n.w, v[k].w));
            out[gi] = o;
        }
    } else if (code == 2) {                       // 3x3 blur: needs neighbors
        float* const sm_b = sm + (b << 8);        // [row16][col16] slice
        #pragma unroll
        for (int k = 0; k < 4; k++) {             // spill patch to smem
            const int fi = l16 + (k << 4);
            *reinterpret_cast<float4*>(
                sm_b + ((fi >> 2) << 4) + ((fi & 3) << 2)) = v[k];
        }
        __syncthreads();                          // uniform: all threads here
        const float inv9 = 1.0f / 9.0f;
        #pragma unroll
        for (int k = 0; k < 4; k++) {
            const int fi  = l16 + (k << 4);
            const int row = fi >> 2;
            const int c0  = (fi & 3) << 2;
            float a0 = 0.f, a1 = 0.f, a2 = 0.f, a3 = 0.f;
            #pragma unroll
            for (int dr = -1; dr <= 1; dr++) {
                const int r = row + dr;
                if (r < 0 || r > 15) continue;    // zero padding in patch
                const float* rp = sm_b + (r << 4);
                const float lft = (c0 > 0)  ? rp[c0 - 1] : 0.0f;
                const float rgt = (c0 < 12) ? rp[c0 + 4] : 0.0f;
                const float m0 = rp[c0], m1 = rp[c0 + 1];
                const float m2 = rp[c0 + 2], m3 = rp[c0 + 3];
                a0 += lft + m0 + m1;
                a1 += m0 + m1 + m2;
                a2 += m1 + m2 + m3;
                a3 += m2 + m3 + rgt;
            }
            out[f4base + (row << 8) + (fi & 3)] =
                make_float4(a0 * inv9, a1 * inv9, a2 * inv9, a3 * inv9);
        }
    } else if (code == 3 || code == 6) {          // brightness variants
        #pragma unroll
        for (int k = 0; k < 4; k++) {
            const int fi = l16 + (k << 4);
            float4 o;
            o.x = clipf(v[k].x * param);
            o.y = clipf(v[k].y * param);
            o.z = clipf(v[k].z * param);
            o.w = clipf(v[k].w * param);
            out[f4base + ((fi >> 2) << 8) + (fi & 3)] = o;
        }
    } else if (code == 4) {                       // contrast about m_pp
        #pragma unroll
        for (int k = 0; k < 4; k++) {
            const int fi = l16 + (k << 4);
            float4 o;
            o.x = clipf(fmaf(v[k].x - mpp, param, mpp));
            o.y = clipf(fmaf(v[k].y - mpp, param, mpp));
            o.z = clipf(fmaf(v[k].z - mpp, param, mpp));
            o.w = clipf(fmaf(v[k].w - mpp, param, mpp));
            out[f4base + ((fi >> 2) << 8) + (fi & 3)] = o;
        }
    } else {                                      // 7: drop -> zeros
        const float4 z = make_float4(0.f, 0.f, 0.f, 0.f);
        #pragma unroll
        for (int k = 0; k < 4; k++) {
            const int fi = l16 + (k << 4);
            out[f4base + ((fi >> 2) << 8) + (fi & 3)] = z;
        }
    }
}

extern "C" void kernel_launch(void* const* d_in, const int* in_sizes, int n_in,
                              void* d_out, int out_size)
{
    fused_kernel<<<4096, 512>>>(
        (const float4*)d_in[0],   // img
        (const float4*)d_in[1],   // noise
        (float4*)d_out,
        (const float*)d_in[2],    // r_strong
        (const float*)d_in[3],    // r_drop
        (const float*)d_in[4],    // r_else
        (const float*)d_in[5],    // bright_f
        (const float*)d_in[6],    // contrast_f
        (const float*)d_in[7],    // slight_f
        (const int*)d_in[8],      // aug_choice
        (const int*)d_in[9]);     // slight_choice
}